// round 3
// baseline (speedup 1.0000x reference)
#include <cuda_runtime.h>
#include <cstdint>
#include <math.h>

#define Bsz 4096
#define Asz 4096
#define Hsz 768
#define Lsz 4

// JAX RNG variant: 1 = threefry_partitionable (modern default), 0 = legacy
#define GUMBEL_PARTITIONABLE 1

// ---------------- scratch (__device__ globals; no allocations allowed) ----
__device__ float d_h[Bsz * Hsz];
__device__ float d_cur[Bsz * Hsz];
__device__ float d_gi[(size_t)Bsz * 3 * Hsz];
__device__ float d_gh[(size_t)Bsz * 3 * Hsz];
__device__ float d_logits[(size_t)Bsz * Asz];
__device__ unsigned int d_mask[(size_t)Bsz * Asz / 32];
__device__ int d_idx[Lsz * Bsz];

// ---------------- threefry2x32 (20 rounds), shared host/device ------------
__host__ __device__ __forceinline__ void threefry2x32(
    unsigned int k0, unsigned int k1, unsigned int x0, unsigned int x1,
    unsigned int& o0, unsigned int& o1)
{
    unsigned int ks0 = k0, ks1 = k1, ks2 = k0 ^ k1 ^ 0x1BD11BDAu;
    x0 += ks0; x1 += ks1;
#define TF_RND(r) { x0 += x1; x1 = (x1 << (r)) | (x1 >> (32 - (r))); x1 ^= x0; }
    TF_RND(13) TF_RND(15) TF_RND(26) TF_RND(6)
    x0 += ks1; x1 += ks2 + 1u;
    TF_RND(17) TF_RND(29) TF_RND(16) TF_RND(24)
    x0 += ks2; x1 += ks0 + 2u;
    TF_RND(13) TF_RND(15) TF_RND(26) TF_RND(6)
    x0 += ks0; x1 += ks1 + 3u;
    TF_RND(17) TF_RND(29) TF_RND(16) TF_RND(24)
    x0 += ks1; x1 += ks2 + 4u;
    TF_RND(13) TF_RND(15) TF_RND(26) TF_RND(6)
    x0 += ks2; x1 += ks0 + 5u;
#undef TF_RND
    o0 = x0; o1 = x1;
}

// ---------------- SGEMM: C[M,N] = A[M,K] @ B[N,K]^T + bias[N] -------------
// BM=BN=128, BK=16, 256 threads, 8x8 per-thread microtile.
#define BM 128
#define BN 128
#define BK 16

__global__ __launch_bounds__(256) void sgemm_tn(
    const float* __restrict__ A, const float* __restrict__ Bw,
    const float* __restrict__ bias, float* __restrict__ C,
    int M, int N, int K)
{
    __shared__ float As[BK][BM];
    __shared__ float Bs[BK][BN];
    const int bm = blockIdx.y * BM;
    const int bn = blockIdx.x * BN;
    const int tid = threadIdx.x;
    const int tr = tid >> 4;   // 0..15
    const int tc = tid & 15;   // 0..15

    float acc[8][8];
#pragma unroll
    for (int i = 0; i < 8; i++)
#pragma unroll
        for (int j = 0; j < 8; j++) acc[i][j] = 0.f;

    for (int k0 = 0; k0 < K; k0 += BK) {
#pragma unroll
        for (int i = 0; i < 2; i++) {
            int s = tid + 256 * i;        // 512 float4 slots
            int row = s >> 2;             // 0..127
            int kq = s & 3;               // 0..3
            float4 v = *(const float4*)(A + (size_t)(bm + row) * K + k0 + kq * 4);
            As[kq * 4 + 0][row] = v.x; As[kq * 4 + 1][row] = v.y;
            As[kq * 4 + 2][row] = v.z; As[kq * 4 + 3][row] = v.w;
        }
#pragma unroll
        for (int i = 0; i < 2; i++) {
            int s = tid + 256 * i;
            int row = s >> 2;
            int kq = s & 3;
            float4 v = *(const float4*)(Bw + (size_t)(bn + row) * K + k0 + kq * 4);
            Bs[kq * 4 + 0][row] = v.x; Bs[kq * 4 + 1][row] = v.y;
            Bs[kq * 4 + 2][row] = v.z; Bs[kq * 4 + 3][row] = v.w;
        }
        __syncthreads();
#pragma unroll
        for (int kk = 0; kk < BK; kk++) {
            float a[8], b[8];
            *(float4*)&a[0] = *(const float4*)&As[kk][tr * 4];
            *(float4*)&a[4] = *(const float4*)&As[kk][64 + tr * 4];
            *(float4*)&b[0] = *(const float4*)&Bs[kk][tc * 4];
            *(float4*)&b[4] = *(const float4*)&Bs[kk][64 + tc * 4];
#pragma unroll
            for (int i = 0; i < 8; i++)
#pragma unroll
                for (int j = 0; j < 8; j++)
                    acc[i][j] = fmaf(a[i], b[j], acc[i][j]);
        }
        __syncthreads();
    }

#pragma unroll
    for (int i = 0; i < 8; i++) {
        int m = bm + ((i < 4) ? (tr * 4 + i) : (64 + tr * 4 + i - 4));
#pragma unroll
        for (int jj = 0; jj < 2; jj++) {
            int n = bn + ((jj == 0) ? (tc * 4) : (64 + tc * 4));
            float4 o;
            o.x = acc[i][jj * 4 + 0] + bias[n + 0];
            o.y = acc[i][jj * 4 + 1] + bias[n + 1];
            o.z = acc[i][jj * 4 + 2] + bias[n + 2];
            o.w = acc[i][jj * 4 + 3] + bias[n + 3];
            *(float4*)(C + (size_t)m * N + n) = o;
        }
    }
}

// ---------------- misc kernels --------------------------------------------
__global__ void zero_out_kernel(float4* out, size_t n4)
{
    size_t i = (size_t)blockIdx.x * blockDim.x + threadIdx.x;
    size_t stride = (size_t)gridDim.x * blockDim.x;
    float4 z = make_float4(0.f, 0.f, 0.f, 0.f);
    for (; i < n4; i += stride) out[i] = z;
}

__global__ void init_state_kernel(const float* __restrict__ cls, int n)
{
    int i = blockIdx.x * blockDim.x + threadIdx.x;
    if (i >= n) return;
    d_h[i] = 0.f;
    d_cur[i] = cls[i];
}

__global__ void init_mask_kernel(const float* __restrict__ x_, int nwords)
{
    int w = blockIdx.x * blockDim.x + threadIdx.x;
    if (w >= nwords) return;
    int b = w >> 7;            // Asz/32 = 128 words per row
    int wa = w & 127;
    const float* xr = x_ + (size_t)b * Asz + wa * 32;
    unsigned int bits = 0;
#pragma unroll
    for (int e = 0; e < 32; e++)
        if (xr[e] != 0.0f) bits |= (1u << e);
    d_mask[w] = bits;
}

__global__ void gru_update_kernel(int n)
{
    int i = blockIdx.x * blockDim.x + threadIdx.x;
    if (i >= n) return;
    int b = i / Hsz, k = i - b * Hsz;
    size_t base = (size_t)b * 3 * Hsz + k;
    float ir = d_gi[base], iz = d_gi[base + Hsz], in_ = d_gi[base + 2 * Hsz];
    float hr = d_gh[base], hz = d_gh[base + Hsz], hn = d_gh[base + 2 * Hsz];
    float r = 1.f / (1.f + expf(-(ir + hr)));
    float z = 1.f / (1.f + expf(-(iz + hz)));
    float nn = tanhf(in_ + r * hn);
    float hv = d_h[i];
    d_h[i] = (1.f - z) * nn + z * hv;
}

__global__ void next_input_kernel(const float* __restrict__ cls,
                                  const float* __restrict__ aew,
                                  int j, int n)
{
    int i = blockIdx.x * blockDim.x + threadIdx.x;
    if (i >= n) return;
    int b = i / Hsz, k = i - b * Hsz;
    int idx = d_idx[j * Bsz + b];
    d_cur[i] = cls[i] + aew[(size_t)idx * Hsz + k];
}

// ---------------- selection: gumbel + mask + argmax -----------------------
__global__ __launch_bounds__(256) void select_step_kernel(
    const float* __restrict__ x_, float* __restrict__ out,
    int j, unsigned int sk0, unsigned int sk1)
{
    int b = blockIdx.x;
    int t = threadIdx.x;
    __shared__ float sv[256];
    __shared__ int si[256];
    __shared__ int s_done;

    if (j > 0) {
        if (t == 0) {
            int p = d_idx[(j - 1) * Bsz + b];
            s_done = (p == 0);
            if (p == 0) {
                d_idx[j * Bsz + b] = 0;
                out[((size_t)b * Lsz + j) * Asz + 0] = 1.0f;
            }
        }
        __syncthreads();
        if (s_done) return;
    }

    float best = __int_as_float(0xff800000);  // -inf
    int bidx = 0x7fffffff;
    const float* lrow = d_logits + (size_t)b * Asz;
    const unsigned int* mrow = d_mask + (size_t)b * (Asz / 32);

    for (int a = t * 16; a < t * 16 + 16; a++) {
        bool valid;
        if (j == 0) valid = (x_[(size_t)b * Asz + a] != 0.0f);
        else        valid = (a == 0) || ((mrow[a >> 5] >> (a & 31)) & 1u);
        if (!valid) continue;

        unsigned long long p = (unsigned long long)b * Asz + (unsigned long long)a;
        unsigned int y0, y1, bits;
#if GUMBEL_PARTITIONABLE
        threefry2x32(sk0, sk1, (unsigned int)(p >> 32), (unsigned int)p, y0, y1);
        bits = y0 ^ y1;
#else
        const unsigned long long NH = (unsigned long long)Bsz * Asz / 2;
        if (p < NH) { threefry2x32(sk0, sk1, (unsigned int)p, (unsigned int)(p + NH), y0, y1); bits = y0; }
        else        { threefry2x32(sk0, sk1, (unsigned int)(p - NH), (unsigned int)p, y0, y1); bits = y1; }
#endif
        float u = __uint_as_float((bits >> 9) | 0x3f800000u) - 1.0f;
        u = fmaxf(u, 1.17549435e-38f);
        float g = -logf(-logf(u));
        float v = lrow[a] + g;
        if (v > best || (v == best && a < bidx)) { best = v; bidx = a; }
    }

    sv[t] = best; si[t] = bidx;
    __syncthreads();
    for (int s = 128; s > 0; s >>= 1) {
        if (t < s) {
            float v2 = sv[t + s]; int i2 = si[t + s];
            if (v2 > sv[t] || (v2 == sv[t] && i2 < si[t])) { sv[t] = v2; si[t] = i2; }
        }
        __syncthreads();
    }
    if (t == 0) {
        int sel = (si[0] == 0x7fffffff) ? 0 : si[0];
        d_idx[j * Bsz + b] = sel;
        d_mask[(size_t)b * (Asz / 32) + (sel >> 5)] &= ~(1u << (sel & 31));
        out[((size_t)b * Lsz + j) * Asz + sel] = 1.0f;
    }
}

// ---------------- launch ---------------------------------------------------
extern "C" void kernel_launch(void* const* d_in, const int* in_sizes, int n_in,
                              void* d_out, int out_size)
{
    const float* cls    = (const float*)d_in[0];
    const float* x_     = (const float*)d_in[1];
    const float* w_ih   = (const float*)d_in[2];   // [3H, H]
    const float* w_hh   = (const float*)d_in[3];   // [3H, H]
    const float* b_ih   = (const float*)d_in[4];   // [3H]
    const float* b_hh   = (const float*)d_in[5];   // [3H]
    const float* head_w = (const float*)d_in[6];   // [A, H]
    const float* head_b = (const float*)d_in[7];   // [A]
    const float* ae_w   = (const float*)d_in[8];   // [A, H]
    float* out = (float*)d_out;

    float *ph, *pcur, *pgi, *pgh, *plog;
    cudaGetSymbolAddress((void**)&ph,   d_h);
    cudaGetSymbolAddress((void**)&pcur, d_cur);
    cudaGetSymbolAddress((void**)&pgi,  d_gi);
    cudaGetSymbolAddress((void**)&pgh,  d_gh);
    cudaGetSymbolAddress((void**)&plog, d_logits);

    // ---- JAX key chain: key = key(42); L x (key, sub = split(key)) ----
    unsigned int k0 = 0u, k1 = 42u;
    unsigned int sub[Lsz][2];
    for (int j = 0; j < Lsz; j++) {
#if GUMBEL_PARTITIONABLE
        unsigned int nk0, nk1, s0, s1;
        threefry2x32(k0, k1, 0u, 0u, nk0, nk1);   // lane 0 -> new key
        threefry2x32(k0, k1, 0u, 1u, s0, s1);     // lane 1 -> subkey
        sub[j][0] = s0; sub[j][1] = s1; k0 = nk0; k1 = nk1;
#else
        unsigned int a0, a1, c0, c1;
        threefry2x32(k0, k1, 0u, 2u, a0, a1);     // lane 0: (0,2)
        threefry2x32(k0, k1, 1u, 3u, c0, c1);     // lane 1: (1,3)
        sub[j][0] = a1; sub[j][1] = c1;           // row 1 of reshape
        k0 = a0; k1 = c0;                         // row 0 of reshape
#endif
    }

    const int BH = Bsz * Hsz;

    zero_out_kernel<<<4096, 256>>>((float4*)out, (size_t)out_size / 4);
    init_state_kernel<<<(BH + 255) / 256, 256>>>(cls, BH);
    init_mask_kernel<<<(Bsz * Asz / 32 + 255) / 256, 256>>>(x_, Bsz * Asz / 32);

    dim3 gGates(3 * Hsz / BN, Bsz / BM);   // (18, 32)
    dim3 gHead(Asz / BN, Bsz / BM);        // (32, 32)

    for (int j = 0; j < Lsz; j++) {
        sgemm_tn<<<gGates, 256>>>(pcur, w_ih, b_ih, pgi, Bsz, 3 * Hsz, Hsz);
        sgemm_tn<<<gGates, 256>>>(ph,   w_hh, b_hh, pgh, Bsz, 3 * Hsz, Hsz);
        gru_update_kernel<<<(BH + 255) / 256, 256>>>(BH);
        sgemm_tn<<<gHead, 256>>>(ph, head_w, head_b, plog, Bsz, Asz, Hsz);
        select_step_kernel<<<Bsz, 256>>>(x_, out, j, sub[j][0], sub[j][1]);
        if (j < Lsz - 1)
            next_input_kernel<<<(BH + 255) / 256, 256>>>(cls, ae_w, j, BH);
    }
}

// round 5
// speedup vs baseline: 1.4214x; 1.4214x over previous
#include <cuda_runtime.h>
#include <cstdint>
#include <math.h>

#define Bsz 4096
#define Asz 4096
#define Hsz 768
#define Lsz 4
#define G3H (3 * Hsz)   // 2304

#define GUMBEL_PARTITIONABLE 1

// ======================= device scratch ===================================
__device__ float d_Gcls[(size_t)Bsz * G3H];
__device__ float d_AEp[(size_t)Asz * G3H];
__device__ float d_gh[(size_t)Bsz * G3H];
__device__ float d_h[(size_t)Bsz * Hsz];
__device__ float d_logits[(size_t)Bsz * Asz];
__device__ unsigned int d_mask[(size_t)Bsz * Asz / 32];
__device__ int d_idx[Lsz * Bsz];

// ======================= threefry2x32 =====================================
__host__ __device__ __forceinline__ void threefry2x32(
    unsigned int k0, unsigned int k1, unsigned int x0, unsigned int x1,
    unsigned int& o0, unsigned int& o1)
{
    unsigned int ks0 = k0, ks1 = k1, ks2 = k0 ^ k1 ^ 0x1BD11BDAu;
    x0 += ks0; x1 += ks1;
#define TF_RND(r) { x0 += x1; x1 = (x1 << (r)) | (x1 >> (32 - (r))); x1 ^= x0; }
    TF_RND(13) TF_RND(15) TF_RND(26) TF_RND(6)
    x0 += ks1; x1 += ks2 + 1u;
    TF_RND(17) TF_RND(29) TF_RND(16) TF_RND(24)
    x0 += ks2; x1 += ks0 + 2u;
    TF_RND(13) TF_RND(15) TF_RND(26) TF_RND(6)
    x0 += ks0; x1 += ks1 + 3u;
    TF_RND(17) TF_RND(29) TF_RND(16) TF_RND(24)
    x0 += ks1; x1 += ks2 + 4u;
    TF_RND(13) TF_RND(15) TF_RND(26) TF_RND(6)
    x0 += ks2; x1 += ks0 + 5u;
#undef TF_RND
    o0 = x0; o1 = x1;
}

// ======================= tf32x3 mma.sync GEMM =============================
// C[M,N] = A[M,K] @ B[N,K]^T (+bias).  fp32 in, tf32 hi/lo split at fragment
// load, 3 products (ah*bh + ah*bl + al*bh), fp32 accum.
// Tile 128x128, BK=16, 2-stage cp.async pipeline, 8 warps (32x64 warp tile).
#define BM 128
#define BN 128
#define BKc 16
#define LDT 20   // smem row stride in floats (16B aligned, conflict-free frags)

#define CP_ASYNC16(dst_u32, src_ptr) \
    asm volatile("cp.async.cg.shared.global [%0], [%1], 16;" :: "r"(dst_u32), "l"(src_ptr) : "memory")
#define CP_COMMIT() asm volatile("cp.async.commit_group;" ::: "memory")
#define CP_WAIT(n)  asm volatile("cp.async.wait_group %0;" :: "n"(n) : "memory")

__device__ __forceinline__ uint32_t f2tf(float x) {
    uint32_t r; asm("cvt.rna.tf32.f32 %0, %1;" : "=r"(r) : "f"(x));
    return r;
}

#define MMA_TF32(c, a, b) \
    asm volatile("mma.sync.aligned.m16n8k8.row.col.f32.tf32.tf32.f32 " \
        "{%0,%1,%2,%3}, {%4,%5,%6,%7}, {%8,%9}, {%0,%1,%2,%3};" \
        : "+f"((c)[0]), "+f"((c)[1]), "+f"((c)[2]), "+f"((c)[3]) \
        : "r"((a)[0]), "r"((a)[1]), "r"((a)[2]), "r"((a)[3]), \
          "r"((b)[0]), "r"((b)[1]))

__global__ void __launch_bounds__(256, 1)
gemm_tf32x3(const float* __restrict__ A, const float* __restrict__ Bw,
            const float* __restrict__ bias, float* __restrict__ C,
            int M, int N, int K)
{
    __shared__ float As[2][BM][LDT];
    __shared__ float Bs[2][BN][LDT];

    const int tid = threadIdx.x;
    const int wid = tid >> 5, lane = tid & 31;
    const int wm = wid >> 1;           // 0..3  -> 32-row slab
    const int wn = wid & 1;            // 0..1  -> 64-col slab
    const int g = lane >> 2;           // groupID 0..7
    const int tg = lane & 3;           // thread-in-group 0..3
    const int bm = blockIdx.y * BM;
    const int bn = blockIdx.x * BN;
    const int NC = K / BKc;            // 48

    uint32_t smA, smB;
    {
        uint32_t a0, b0;
        asm("{ .reg .u64 t; cvta.to.shared.u64 t, %1; cvt.u32.u64 %0, t; }"
            : "=r"(a0) : "l"(&As[0][0][0]));
        asm("{ .reg .u64 t; cvta.to.shared.u64 t, %1; cvt.u32.u64 %0, t; }"
            : "=r"(b0) : "l"(&Bs[0][0][0]));
        smA = a0; smB = b0;
    }

    float acc[2][8][4];
#pragma unroll
    for (int i = 0; i < 2; i++)
#pragma unroll
        for (int j = 0; j < 8; j++)
#pragma unroll
            for (int k = 0; k < 4; k++) acc[i][j][k] = 0.f;

    // ---- load chunk 0 ----
    {
        const int r = tid >> 2, q = tid & 3;
#pragma unroll
        for (int h = 0; h < 2; h++) {
            int rr = r + h * 64;
            CP_ASYNC16(smA + (uint32_t)((0 * BM + rr) * LDT + q * 4) * 4,
                       A + (size_t)(bm + rr) * K + q * 4);
            CP_ASYNC16(smB + (uint32_t)((0 * BN + rr) * LDT + q * 4) * 4,
                       Bw + (size_t)(bn + rr) * K + q * 4);
        }
        CP_COMMIT();
    }

    for (int c = 0; c < NC; ++c) {
        if (c + 1 < NC) {
            const int r = tid >> 2, q = tid & 3;
            const int k0 = (c + 1) * BKc;
            const int nb = (c + 1) & 1;
#pragma unroll
            for (int h = 0; h < 2; h++) {
                int rr = r + h * 64;
                CP_ASYNC16(smA + (uint32_t)((nb * BM + rr) * LDT + q * 4) * 4,
                           A + (size_t)(bm + rr) * K + k0 + q * 4);
                CP_ASYNC16(smB + (uint32_t)((nb * BN + rr) * LDT + q * 4) * 4,
                           Bw + (size_t)(bn + rr) * K + k0 + q * 4);
            }
            CP_COMMIT();
            CP_WAIT(1);
        } else {
            CP_WAIT(0);
        }
        __syncthreads();

        const int cb = c & 1;
#pragma unroll
        for (int ks = 0; ks < 2; ks++) {
            const int kk = ks * 8;
            uint32_t ahi[2][4], alo[2][4], bhi[8][2], blo[8][2];
#pragma unroll
            for (int mt = 0; mt < 2; mt++) {
                const int r0 = wm * 32 + mt * 16 + g;
                float x0 = As[cb][r0][kk + tg];
                float x1 = As[cb][r0 + 8][kk + tg];
                float x2 = As[cb][r0][kk + tg + 4];
                float x3 = As[cb][r0 + 8][kk + tg + 4];
                ahi[mt][0] = f2tf(x0); alo[mt][0] = f2tf(x0 - __uint_as_float(ahi[mt][0]));
                ahi[mt][1] = f2tf(x1); alo[mt][1] = f2tf(x1 - __uint_as_float(ahi[mt][1]));
                ahi[mt][2] = f2tf(x2); alo[mt][2] = f2tf(x2 - __uint_as_float(ahi[mt][2]));
                ahi[mt][3] = f2tf(x3); alo[mt][3] = f2tf(x3 - __uint_as_float(ahi[mt][3]));
            }
#pragma unroll
            for (int nt = 0; nt < 8; nt++) {
                const int n0 = wn * 64 + nt * 8 + g;
                float y0 = Bs[cb][n0][kk + tg];
                float y1 = Bs[cb][n0][kk + tg + 4];
                bhi[nt][0] = f2tf(y0); blo[nt][0] = f2tf(y0 - __uint_as_float(bhi[nt][0]));
                bhi[nt][1] = f2tf(y1); blo[nt][1] = f2tf(y1 - __uint_as_float(bhi[nt][1]));
            }
#pragma unroll
            for (int mt = 0; mt < 2; mt++)
#pragma unroll
                for (int nt = 0; nt < 8; nt++) {
                    MMA_TF32(acc[mt][nt], ahi[mt], blo[nt]);
                    MMA_TF32(acc[mt][nt], alo[mt], bhi[nt]);
                    MMA_TF32(acc[mt][nt], ahi[mt], bhi[nt]);
                }
        }
        __syncthreads();
    }

    // ---- epilogue ----
#pragma unroll
    for (int mt = 0; mt < 2; mt++) {
        const int r0 = bm + wm * 32 + mt * 16 + g;
#pragma unroll
        for (int nt = 0; nt < 8; nt++) {
            const int n0 = bn + wn * 64 + nt * 8 + tg * 2;
            float bx = 0.f, by = 0.f;
            if (bias) { bx = bias[n0]; by = bias[n0 + 1]; }
            float2 v0 = make_float2(acc[mt][nt][0] + bx, acc[mt][nt][1] + by);
            float2 v1 = make_float2(acc[mt][nt][2] + bx, acc[mt][nt][3] + by);
            *(float2*)(C + (size_t)r0 * N + n0) = v0;
            *(float2*)(C + (size_t)(r0 + 8) * N + n0) = v1;
        }
    }
}

// ======================= elementwise kernels ==============================
__global__ void zero_out_kernel(float4* out, size_t n4)
{
    size_t i = (size_t)blockIdx.x * blockDim.x + threadIdx.x;
    size_t stride = (size_t)gridDim.x * blockDim.x;
    float4 z = make_float4(0.f, 0.f, 0.f, 0.f);
    for (; i < n4; i += stride) out[i] = z;
}

__global__ void init_mask_kernel(const float* __restrict__ x_, int nwords)
{
    int w = blockIdx.x * blockDim.x + threadIdx.x;
    if (w >= nwords) return;
    int b = w >> 7;
    int wa = w & 127;
    const float* xr = x_ + (size_t)b * Asz + wa * 32;
    unsigned int bits = 0;
#pragma unroll
    for (int e = 0; e < 32; e++)
        if (xr[e] != 0.0f) bits |= (1u << e);
    d_mask[w] = bits;
}

// Step 0: h_prev = 0 -> gh = b_hh exactly; h = (1-z)*n.
__global__ void gru_step0_kernel(const float* __restrict__ b_hh, int n)
{
    int i = blockIdx.x * blockDim.x + threadIdx.x;
    if (i >= n) return;
    int b = i / Hsz, k = i - b * Hsz;
    const float* gg = d_Gcls + (size_t)b * G3H;
    float ir = gg[k], iz = gg[Hsz + k], inn = gg[2 * Hsz + k];
    float hr = b_hh[k], hz = b_hh[Hsz + k], hn = b_hh[2 * Hsz + k];
    float r = 1.f / (1.f + expf(-(ir + hr)));
    float z = 1.f / (1.f + expf(-(iz + hz)));
    float nn = tanhf(inn + r * hn);
    d_h[i] = (1.f - z) * nn;
}

// Step j>=1: gi = G_cls + AE_proj[idx_{j-1}]; gh from GEMM (incl. b_hh).
__global__ void gru_step_kernel(int j, int n)
{
    int i = blockIdx.x * blockDim.x + threadIdx.x;
    if (i >= n) return;
    int b = i / Hsz, k = i - b * Hsz;
    int idx = d_idx[(j - 1) * Bsz + b];
    const float* gg = d_Gcls + (size_t)b * G3H;
    const float* ap = d_AEp + (size_t)idx * G3H;
    const float* gh = d_gh + (size_t)b * G3H;
    float ir = gg[k] + ap[k];
    float iz = gg[Hsz + k] + ap[Hsz + k];
    float inn = gg[2 * Hsz + k] + ap[2 * Hsz + k];
    float hr = gh[k], hz = gh[Hsz + k], hn = gh[2 * Hsz + k];
    float r = 1.f / (1.f + expf(-(ir + hr)));
    float z = 1.f / (1.f + expf(-(iz + hz)));
    float nn = tanhf(inn + r * hn);
    d_h[i] = (1.f - z) * nn + z * d_h[i];
}

// ---------------- selection: gumbel + mask + argmax -----------------------
__global__ __launch_bounds__(256) void select_step_kernel(
    const float* __restrict__ x_, float* __restrict__ out,
    int j, unsigned int sk0, unsigned int sk1)
{
    int b = blockIdx.x;
    int t = threadIdx.x;
    __shared__ float sv[256];
    __shared__ int si[256];
    __shared__ int s_done;

    if (j > 0) {
        if (t == 0) {
            int p = d_idx[(j - 1) * Bsz + b];
            s_done = (p == 0);
            if (p == 0) {
                d_idx[j * Bsz + b] = 0;
                out[((size_t)b * Lsz + j) * Asz + 0] = 1.0f;
            }
        }
        __syncthreads();
        if (s_done) return;
    }

    float best = __int_as_float(0xff800000);
    int bidx = 0x7fffffff;
    const float* lrow = d_logits + (size_t)b * Asz;
    const unsigned int* mrow = d_mask + (size_t)b * (Asz / 32);

    for (int a = t * 16; a < t * 16 + 16; a++) {
        bool valid;
        if (j == 0) valid = (x_[(size_t)b * Asz + a] != 0.0f);
        else        valid = (a == 0) || ((mrow[a >> 5] >> (a & 31)) & 1u);
        if (!valid) continue;

        unsigned long long p = (unsigned long long)b * Asz + (unsigned long long)a;
        unsigned int y0, y1, bits;
#if GUMBEL_PARTITIONABLE
        threefry2x32(sk0, sk1, (unsigned int)(p >> 32), (unsigned int)p, y0, y1);
        bits = y0 ^ y1;
#else
        const unsigned long long NH = (unsigned long long)Bsz * Asz / 2;
        if (p < NH) { threefry2x32(sk0, sk1, (unsigned int)p, (unsigned int)(p + NH), y0, y1); bits = y0; }
        else        { threefry2x32(sk0, sk1, (unsigned int)(p - NH), (unsigned int)p, y0, y1); bits = y1; }
#endif
        float u = __uint_as_float((bits >> 9) | 0x3f800000u) - 1.0f;
        u = fmaxf(u, 1.17549435e-38f);
        float gmb = -logf(-logf(u));
        float v = lrow[a] + gmb;
        if (v > best || (v == best && a < bidx)) { best = v; bidx = a; }
    }

    sv[t] = best; si[t] = bidx;
    __syncthreads();
    for (int s = 128; s > 0; s >>= 1) {
        if (t < s) {
            float v2 = sv[t + s]; int i2 = si[t + s];
            if (v2 > sv[t] || (v2 == sv[t] && i2 < si[t])) { sv[t] = v2; si[t] = i2; }
        }
        __syncthreads();
    }
    if (t == 0) {
        int sel = (si[0] == 0x7fffffff) ? 0 : si[0];
        d_idx[j * Bsz + b] = sel;
        d_mask[(size_t)b * (Asz / 32) + (sel >> 5)] &= ~(1u << (sel & 31));
        out[((size_t)b * Lsz + j) * Asz + sel] = 1.0f;
    }
}

// ======================= launch ===========================================
extern "C" void kernel_launch(void* const* d_in, const int* in_sizes, int n_in,
                              void* d_out, int out_size)
{
    const float* cls    = (const float*)d_in[0];
    const float* x_     = (const float*)d_in[1];
    const float* w_ih   = (const float*)d_in[2];
    const float* w_hh   = (const float*)d_in[3];
    const float* b_ih   = (const float*)d_in[4];
    const float* b_hh   = (const float*)d_in[5];
    const float* head_w = (const float*)d_in[6];
    const float* head_b = (const float*)d_in[7];
    const float* ae_w   = (const float*)d_in[8];
    float* out = (float*)d_out;

    float *p_Gcls, *p_AEp, *p_gh, *p_h, *p_logits;
    cudaGetSymbolAddress((void**)&p_Gcls,   d_Gcls);
    cudaGetSymbolAddress((void**)&p_AEp,    d_AEp);
    cudaGetSymbolAddress((void**)&p_gh,     d_gh);
    cudaGetSymbolAddress((void**)&p_h,      d_h);
    cudaGetSymbolAddress((void**)&p_logits, d_logits);

    // JAX key chain
    unsigned int k0 = 0u, k1 = 42u;
    unsigned int sub[Lsz][2];
    for (int j = 0; j < Lsz; j++) {
#if GUMBEL_PARTITIONABLE
        unsigned int nk0, nk1, s0, s1;
        threefry2x32(k0, k1, 0u, 0u, nk0, nk1);
        threefry2x32(k0, k1, 0u, 1u, s0, s1);
        sub[j][0] = s0; sub[j][1] = s1; k0 = nk0; k1 = nk1;
#else
        unsigned int a0, a1, c0, c1;
        threefry2x32(k0, k1, 0u, 2u, a0, a1);
        threefry2x32(k0, k1, 1u, 3u, c0, c1);
        sub[j][0] = a1; sub[j][1] = c1;
        k0 = a0; k1 = c0;
#endif
    }

    const int BH = Bsz * Hsz;

    zero_out_kernel<<<4096, 256>>>((float4*)out, (size_t)out_size / 4);
    init_mask_kernel<<<(Bsz * Asz / 32 + 255) / 256, 256>>>(x_, Bsz * Asz / 32);

    dim3 gGates(G3H / BN, Bsz / BM);   // (18, 32)
    dim3 gHead(Asz / BN, Bsz / BM);    // (32, 32)

    // Precompute (once): G_cls = cls @ w_ih^T + b_ih ; AE_proj = ae_w @ w_ih^T
    gemm_tf32x3<<<gGates, 256>>>(cls,  w_ih, b_ih,   p_Gcls, Bsz, G3H, Hsz);
    gemm_tf32x3<<<gGates, 256>>>(ae_w, w_ih, nullptr, p_AEp, Asz, G3H, Hsz);

    // Step 0
    gru_step0_kernel<<<(BH + 255) / 256, 256>>>(b_hh, BH);
    gemm_tf32x3<<<gHead, 256>>>(p_h, head_w, head_b, p_logits, Bsz, Asz, Hsz);
    select_step_kernel<<<Bsz, 256>>>(x_, out, 0, sub[0][0], sub[0][1]);

    for (int j = 1; j < Lsz; j++) {
        gemm_tf32x3<<<gGates, 256>>>(p_h, w_hh, b_hh, p_gh, Bsz, G3H, Hsz);
        gru_step_kernel<<<(BH + 255) / 256, 256>>>(j, BH);
        gemm_tf32x3<<<gHead, 256>>>(p_h, head_w, head_b, p_logits, Bsz, Asz, Hsz);
        select_step_kernel<<<Bsz, 256>>>(x_, out, j, sub[j][0], sub[j][1]);
    }
}

// round 6
// speedup vs baseline: 1.5065x; 1.0599x over previous
#include <cuda_runtime.h>
#include <cstdint>
#include <math.h>

#define Bsz 4096
#define Asz 4096
#define Hsz 768
#define Lsz 4
#define G3H (3 * Hsz)   // 2304

#define GUMBEL_PARTITIONABLE 1

// ======================= device scratch ===================================
__device__ float d_Gcls[(size_t)Bsz * G3H];
__device__ float d_AEp[(size_t)Asz * G3H];
__device__ float d_gh[(size_t)Bsz * G3H];
__device__ float d_h[(size_t)Bsz * Hsz];
__device__ float d_logits[(size_t)Bsz * Asz];
__device__ unsigned int d_mask[(size_t)Bsz * Asz / 32];
__device__ int d_idx[Lsz * Bsz];

// ======================= threefry2x32 =====================================
__host__ __device__ __forceinline__ void threefry2x32(
    unsigned int k0, unsigned int k1, unsigned int x0, unsigned int x1,
    unsigned int& o0, unsigned int& o1)
{
    unsigned int ks0 = k0, ks1 = k1, ks2 = k0 ^ k1 ^ 0x1BD11BDAu;
    x0 += ks0; x1 += ks1;
#define TF_RND(r) { x0 += x1; x1 = (x1 << (r)) | (x1 >> (32 - (r))); x1 ^= x0; }
    TF_RND(13) TF_RND(15) TF_RND(26) TF_RND(6)
    x0 += ks1; x1 += ks2 + 1u;
    TF_RND(17) TF_RND(29) TF_RND(16) TF_RND(24)
    x0 += ks2; x1 += ks0 + 2u;
    TF_RND(13) TF_RND(15) TF_RND(26) TF_RND(6)
    x0 += ks0; x1 += ks1 + 3u;
    TF_RND(17) TF_RND(29) TF_RND(16) TF_RND(24)
    x0 += ks1; x1 += ks2 + 4u;
    TF_RND(13) TF_RND(15) TF_RND(26) TF_RND(6)
    x0 += ks2; x1 += ks0 + 5u;
#undef TF_RND
    o0 = x0; o1 = x1;
}

// ======================= tf32x3 mma.sync GEMM =============================
// C[M,N] = A[M,K] @ B[N,K]^T (+bias).  fp32 in; hi = mask-truncated tf32,
// lo = cvt(x - hi); 3 products (ah*bl + al*bh + ah*bh), fp32 accum.
// Tile 128x128, BK=16, 2-stage cp.async pipeline, 8 warps (32x64 warp tile).
// MMAs issued in 3 independent passes (dep distance 16) to keep HMMA pipe full.
#define BM 128
#define BN 128
#define BKc 16
#define LDT 20   // smem row stride in floats

#define CP_ASYNC16(dst_u32, src_ptr) \
    asm volatile("cp.async.cg.shared.global [%0], [%1], 16;" :: "r"(dst_u32), "l"(src_ptr) : "memory")
#define CP_COMMIT() asm volatile("cp.async.commit_group;" ::: "memory")
#define CP_WAIT(n)  asm volatile("cp.async.wait_group %0;" :: "n"(n) : "memory")

__device__ __forceinline__ uint32_t f2tf(float x) {
    uint32_t r; asm("cvt.rna.tf32.f32 %0, %1;" : "=r"(r) : "f"(x));
    return r;
}
// hi via mantissa truncation (exactly tf32-representable), lo via cvt.
__device__ __forceinline__ void split_hl(float x, uint32_t& hi, uint32_t& lo) {
    hi = __float_as_uint(x) & 0xFFFFE000u;
    lo = f2tf(x - __uint_as_float(hi));
}

#define MMA_TF32(c, a, b) \
    asm volatile("mma.sync.aligned.m16n8k8.row.col.f32.tf32.tf32.f32 " \
        "{%0,%1,%2,%3}, {%4,%5,%6,%7}, {%8,%9}, {%0,%1,%2,%3};" \
        : "+f"((c)[0]), "+f"((c)[1]), "+f"((c)[2]), "+f"((c)[3]) \
        : "r"((a)[0]), "r"((a)[1]), "r"((a)[2]), "r"((a)[3]), \
          "r"((b)[0]), "r"((b)[1]))

__global__ void __launch_bounds__(256, 1)
gemm_tf32x3(const float* __restrict__ A, const float* __restrict__ Bw,
            const float* __restrict__ bias, float* __restrict__ C,
            int M, int N, int K)
{
    __shared__ float As[2][BM][LDT];
    __shared__ float Bs[2][BN][LDT];

    const int tid = threadIdx.x;
    const int wid = tid >> 5, lane = tid & 31;
    const int wm = wid >> 1;           // 0..3
    const int wn = wid & 1;            // 0..1
    const int g = lane >> 2;           // 0..7
    const int tg = lane & 3;           // 0..3
    const int bm = blockIdx.y * BM;
    const int bn = blockIdx.x * BN;
    const int NC = K / BKc;            // 48

    uint32_t smA, smB;
    {
        uint32_t a0, b0;
        asm("{ .reg .u64 t; cvta.to.shared.u64 t, %1; cvt.u32.u64 %0, t; }"
            : "=r"(a0) : "l"(&As[0][0][0]));
        asm("{ .reg .u64 t; cvta.to.shared.u64 t, %1; cvt.u32.u64 %0, t; }"
            : "=r"(b0) : "l"(&Bs[0][0][0]));
        smA = a0; smB = b0;
    }

    float acc[2][8][4];
#pragma unroll
    for (int i = 0; i < 2; i++)
#pragma unroll
        for (int j = 0; j < 8; j++)
#pragma unroll
            for (int k = 0; k < 4; k++) acc[i][j][k] = 0.f;

    // ---- load chunk 0 ----
    {
        const int r = tid >> 2, q = tid & 3;
#pragma unroll
        for (int h = 0; h < 2; h++) {
            int rr = r + h * 64;
            CP_ASYNC16(smA + (uint32_t)((0 * BM + rr) * LDT + q * 4) * 4,
                       A + (size_t)(bm + rr) * K + q * 4);
            CP_ASYNC16(smB + (uint32_t)((0 * BN + rr) * LDT + q * 4) * 4,
                       Bw + (size_t)(bn + rr) * K + q * 4);
        }
        CP_COMMIT();
    }

    for (int c = 0; c < NC; ++c) {
        if (c + 1 < NC) {
            const int r = tid >> 2, q = tid & 3;
            const int k0 = (c + 1) * BKc;
            const int nb = (c + 1) & 1;
#pragma unroll
            for (int h = 0; h < 2; h++) {
                int rr = r + h * 64;
                CP_ASYNC16(smA + (uint32_t)((nb * BM + rr) * LDT + q * 4) * 4,
                           A + (size_t)(bm + rr) * K + k0 + q * 4);
                CP_ASYNC16(smB + (uint32_t)((nb * BN + rr) * LDT + q * 4) * 4,
                           Bw + (size_t)(bn + rr) * K + k0 + q * 4);
            }
            CP_COMMIT();
            CP_WAIT(1);
        } else {
            CP_WAIT(0);
        }
        __syncthreads();

        const int cb = c & 1;
#pragma unroll
        for (int ks = 0; ks < 2; ks++) {
            const int kk = ks * 8;
            uint32_t ahi[2][4], alo[2][4], bhi[8][2], blo[8][2];
#pragma unroll
            for (int mt = 0; mt < 2; mt++) {
                const int r0 = wm * 32 + mt * 16 + g;
                float x0 = As[cb][r0][kk + tg];
                float x1 = As[cb][r0 + 8][kk + tg];
                float x2 = As[cb][r0][kk + tg + 4];
                float x3 = As[cb][r0 + 8][kk + tg + 4];
                split_hl(x0, ahi[mt][0], alo[mt][0]);
                split_hl(x1, ahi[mt][1], alo[mt][1]);
                split_hl(x2, ahi[mt][2], alo[mt][2]);
                split_hl(x3, ahi[mt][3], alo[mt][3]);
            }
#pragma unroll
            for (int nt = 0; nt < 8; nt++) {
                const int n0 = wn * 64 + nt * 8 + g;
                float y0 = Bs[cb][n0][kk + tg];
                float y1 = Bs[cb][n0][kk + tg + 4];
                split_hl(y0, bhi[nt][0], blo[nt][0]);
                split_hl(y1, bhi[nt][1], blo[nt][1]);
            }
            // 3 passes: per-accumulator dependency distance = 16 MMAs
#pragma unroll
            for (int mt = 0; mt < 2; mt++)
#pragma unroll
                for (int nt = 0; nt < 8; nt++)
                    MMA_TF32(acc[mt][nt], ahi[mt], blo[nt]);
#pragma unroll
            for (int mt = 0; mt < 2; mt++)
#pragma unroll
                for (int nt = 0; nt < 8; nt++)
                    MMA_TF32(acc[mt][nt], alo[mt], bhi[nt]);
#pragma unroll
            for (int mt = 0; mt < 2; mt++)
#pragma unroll
                for (int nt = 0; nt < 8; nt++)
                    MMA_TF32(acc[mt][nt], ahi[mt], bhi[nt]);
        }
        __syncthreads();
    }

    // ---- epilogue ----
#pragma unroll
    for (int mt = 0; mt < 2; mt++) {
        const int r0 = bm + wm * 32 + mt * 16 + g;
#pragma unroll
        for (int nt = 0; nt < 8; nt++) {
            const int n0 = bn + wn * 64 + nt * 8 + tg * 2;
            float bx = 0.f, by = 0.f;
            if (bias) { bx = bias[n0]; by = bias[n0 + 1]; }
            float2 v0 = make_float2(acc[mt][nt][0] + bx, acc[mt][nt][1] + by);
            float2 v1 = make_float2(acc[mt][nt][2] + bx, acc[mt][nt][3] + by);
            *(float2*)(C + (size_t)r0 * N + n0) = v0;
            *(float2*)(C + (size_t)(r0 + 8) * N + n0) = v1;
        }
    }
}

// ======================= elementwise kernels ==============================
__global__ void zero_out_kernel(float4* out, size_t n4)
{
    size_t i = (size_t)blockIdx.x * blockDim.x + threadIdx.x;
    size_t stride = (size_t)gridDim.x * blockDim.x;
    float4 z = make_float4(0.f, 0.f, 0.f, 0.f);
    for (; i < n4; i += stride) out[i] = z;
}

__global__ void init_mask_kernel(const float* __restrict__ x_, int nwords)
{
    int w = blockIdx.x * blockDim.x + threadIdx.x;
    if (w >= nwords) return;
    int b = w >> 7;
    int wa = w & 127;
    const float* xr = x_ + (size_t)b * Asz + wa * 32;
    unsigned int bits = 0;
#pragma unroll
    for (int e = 0; e < 32; e++)
        if (xr[e] != 0.0f) bits |= (1u << e);
    d_mask[w] = bits;
}

// Step 0: h_prev = 0 -> gh = b_hh exactly; h = (1-z)*n.
__global__ void gru_step0_kernel(const float* __restrict__ b_hh, int n)
{
    int i = blockIdx.x * blockDim.x + threadIdx.x;
    if (i >= n) return;
    int b = i / Hsz, k = i - b * Hsz;
    const float* gg = d_Gcls + (size_t)b * G3H;
    float ir = gg[k], iz = gg[Hsz + k], inn = gg[2 * Hsz + k];
    float hr = b_hh[k], hz = b_hh[Hsz + k], hn = b_hh[2 * Hsz + k];
    float r = 1.f / (1.f + expf(-(ir + hr)));
    float z = 1.f / (1.f + expf(-(iz + hz)));
    float nn = tanhf(inn + r * hn);
    d_h[i] = (1.f - z) * nn;
}

// Step j>=1: gi = G_cls + AE_proj[idx_{j-1}]; gh from GEMM (incl. b_hh).
__global__ void gru_step_kernel(int j, int n)
{
    int i = blockIdx.x * blockDim.x + threadIdx.x;
    if (i >= n) return;
    int b = i / Hsz, k = i - b * Hsz;
    int idx = d_idx[(j - 1) * Bsz + b];
    const float* gg = d_Gcls + (size_t)b * G3H;
    const float* ap = d_AEp + (size_t)idx * G3H;
    const float* gh = d_gh + (size_t)b * G3H;
    float ir = gg[k] + ap[k];
    float iz = gg[Hsz + k] + ap[Hsz + k];
    float inn = gg[2 * Hsz + k] + ap[2 * Hsz + k];
    float hr = gh[k], hz = gh[Hsz + k], hn = gh[2 * Hsz + k];
    float r = 1.f / (1.f + expf(-(ir + hr)));
    float z = 1.f / (1.f + expf(-(iz + hz)));
    float nn = tanhf(inn + r * hn);
    d_h[i] = (1.f - z) * nn + z * d_h[i];
}

// ---------------- selection: gumbel + mask + argmax -----------------------
__global__ __launch_bounds__(256) void select_step_kernel(
    const float* __restrict__ x_, float* __restrict__ out,
    int j, unsigned int sk0, unsigned int sk1)
{
    int b = blockIdx.x;
    int t = threadIdx.x;
    __shared__ float sv[256];
    __shared__ int si[256];
    __shared__ int s_done;

    if (j > 0) {
        if (t == 0) {
            int p = d_idx[(j - 1) * Bsz + b];
            s_done = (p == 0);
            if (p == 0) {
                d_idx[j * Bsz + b] = 0;
                out[((size_t)b * Lsz + j) * Asz + 0] = 1.0f;
            }
        }
        __syncthreads();
        if (s_done) return;
    }

    float best = __int_as_float(0xff800000);
    int bidx = 0x7fffffff;
    const float* lrow = d_logits + (size_t)b * Asz;
    const unsigned int* mrow = d_mask + (size_t)b * (Asz / 32);

    for (int a = t; a < Asz; a += 256) {          // coalesced stride
        bool valid;
        if (j == 0) valid = (x_[(size_t)b * Asz + a] != 0.0f);
        else        valid = (a == 0) || ((mrow[a >> 5] >> (a & 31)) & 1u);
        if (!valid) continue;

        unsigned long long p = (unsigned long long)b * Asz + (unsigned long long)a;
        unsigned int y0, y1, bits;
#if GUMBEL_PARTITIONABLE
        threefry2x32(sk0, sk1, (unsigned int)(p >> 32), (unsigned int)p, y0, y1);
        bits = y0 ^ y1;
#else
        const unsigned long long NH = (unsigned long long)Bsz * Asz / 2;
        if (p < NH) { threefry2x32(sk0, sk1, (unsigned int)p, (unsigned int)(p + NH), y0, y1); bits = y0; }
        else        { threefry2x32(sk0, sk1, (unsigned int)(p - NH), (unsigned int)p, y0, y1); bits = y1; }
#endif
        float u = __uint_as_float((bits >> 9) | 0x3f800000u) - 1.0f;
        u = fmaxf(u, 1.17549435e-38f);
        float gmb = -logf(-logf(u));
        float v = lrow[a] + gmb;
        if (v > best || (v == best && a < bidx)) { best = v; bidx = a; }
    }

    sv[t] = best; si[t] = bidx;
    __syncthreads();
    for (int s = 128; s > 0; s >>= 1) {
        if (t < s) {
            float v2 = sv[t + s]; int i2 = si[t + s];
            if (v2 > sv[t] || (v2 == sv[t] && i2 < si[t])) { sv[t] = v2; si[t] = i2; }
        }
        __syncthreads();
    }
    if (t == 0) {
        int sel = (si[0] == 0x7fffffff) ? 0 : si[0];
        d_idx[j * Bsz + b] = sel;
        d_mask[(size_t)b * (Asz / 32) + (sel >> 5)] &= ~(1u << (sel & 31));
        out[((size_t)b * Lsz + j) * Asz + sel] = 1.0f;
    }
}

// ======================= launch ===========================================
extern "C" void kernel_launch(void* const* d_in, const int* in_sizes, int n_in,
                              void* d_out, int out_size)
{
    const float* cls    = (const float*)d_in[0];
    const float* x_     = (const float*)d_in[1];
    const float* w_ih   = (const float*)d_in[2];
    const float* w_hh   = (const float*)d_in[3];
    const float* b_ih   = (const float*)d_in[4];
    const float* b_hh   = (const float*)d_in[5];
    const float* head_w = (const float*)d_in[6];
    const float* head_b = (const float*)d_in[7];
    const float* ae_w   = (const float*)d_in[8];
    float* out = (float*)d_out;

    float *p_Gcls, *p_AEp, *p_gh, *p_h, *p_logits;
    cudaGetSymbolAddress((void**)&p_Gcls,   d_Gcls);
    cudaGetSymbolAddress((void**)&p_AEp,    d_AEp);
    cudaGetSymbolAddress((void**)&p_gh,     d_gh);
    cudaGetSymbolAddress((void**)&p_h,      d_h);
    cudaGetSymbolAddress((void**)&p_logits, d_logits);

    // JAX key chain
    unsigned int k0 = 0u, k1 = 42u;
    unsigned int sub[Lsz][2];
    for (int j = 0; j < Lsz; j++) {
#if GUMBEL_PARTITIONABLE
        unsigned int nk0, nk1, s0, s1;
        threefry2x32(k0, k1, 0u, 0u, nk0, nk1);
        threefry2x32(k0, k1, 0u, 1u, s0, s1);
        sub[j][0] = s0; sub[j][1] = s1; k0 = nk0; k1 = nk1;
#else
        unsigned int a0, a1, c0, c1;
        threefry2x32(k0, k1, 0u, 2u, a0, a1);
        threefry2x32(k0, k1, 1u, 3u, c0, c1);
        sub[j][0] = a1; sub[j][1] = c1;
        k0 = a0; k1 = c0;
#endif
    }

    const int BH = Bsz * Hsz;

    zero_out_kernel<<<4096, 256>>>((float4*)out, (size_t)out_size / 4);
    init_mask_kernel<<<(Bsz * Asz / 32 + 255) / 256, 256>>>(x_, Bsz * Asz / 32);

    dim3 gGates(G3H / BN, Bsz / BM);   // (18, 32)
    dim3 gHead(Asz / BN, Bsz / BM);    // (32, 32)

    // Precompute (once): G_cls = cls @ w_ih^T + b_ih ; AE_proj = ae_w @ w_ih^T
    gemm_tf32x3<<<gGates, 256>>>(cls,  w_ih, b_ih,   p_Gcls, Bsz, G3H, Hsz);
    gemm_tf32x3<<<gGates, 256>>>(ae_w, w_ih, nullptr, p_AEp, Asz, G3H, Hsz);

    // Step 0
    gru_step0_kernel<<<(BH + 255) / 256, 256>>>(b_hh, BH);
    gemm_tf32x3<<<gHead, 256>>>(p_h, head_w, head_b, p_logits, Bsz, Asz, Hsz);
    select_step_kernel<<<Bsz, 256>>>(x_, out, 0, sub[0][0], sub[0][1]);

    for (int j = 1; j < Lsz; j++) {
        gemm_tf32x3<<<gGates, 256>>>(p_h, w_hh, b_hh, p_gh, Bsz, G3H, Hsz);
        gru_step_kernel<<<(BH + 255) / 256, 256>>>(j, BH);
        gemm_tf32x3<<<gHead, 256>>>(p_h, head_w, head_b, p_logits, Bsz, Asz, Hsz);
        select_step_kernel<<<Bsz, 256>>>(x_, out, j, sub[j][0], sub[j][1]);
    }
}

// round 7
// speedup vs baseline: 1.6724x; 1.1101x over previous
#include <cuda_runtime.h>
#include <cstdint>
#include <math.h>

#define Bsz 4096
#define Asz 4096
#define Hsz 768
#define Lsz 4
#define G3H (3 * Hsz)   // 2304

#define GUMBEL_PARTITIONABLE 1

// ======================= device scratch ===================================
__device__ float d_Gcls[(size_t)Bsz * G3H];
__device__ float d_AEp[(size_t)Asz * G3H];
__device__ float d_gh[(size_t)Bsz * G3H];
__device__ float d_h[(size_t)Bsz * Hsz];
__device__ float d_logits[(size_t)Bsz * Asz];
__device__ unsigned int d_mask[(size_t)Bsz * Asz / 32];
__device__ int d_idx[Lsz * Bsz];

// ======================= threefry2x32 =====================================
__host__ __device__ __forceinline__ void threefry2x32(
    unsigned int k0, unsigned int k1, unsigned int x0, unsigned int x1,
    unsigned int& o0, unsigned int& o1)
{
    unsigned int ks0 = k0, ks1 = k1, ks2 = k0 ^ k1 ^ 0x1BD11BDAu;
    x0 += ks0; x1 += ks1;
#define TF_RND(r) { x0 += x1; x1 = (x1 << (r)) | (x1 >> (32 - (r))); x1 ^= x0; }
    TF_RND(13) TF_RND(15) TF_RND(26) TF_RND(6)
    x0 += ks1; x1 += ks2 + 1u;
    TF_RND(17) TF_RND(29) TF_RND(16) TF_RND(24)
    x0 += ks2; x1 += ks0 + 2u;
    TF_RND(13) TF_RND(15) TF_RND(26) TF_RND(6)
    x0 += ks0; x1 += ks1 + 3u;
    TF_RND(17) TF_RND(29) TF_RND(16) TF_RND(24)
    x0 += ks1; x1 += ks2 + 4u;
    TF_RND(13) TF_RND(15) TF_RND(26) TF_RND(6)
    x0 += ks2; x1 += ks0 + 5u;
#undef TF_RND
    o0 = x0; o1 = x1;
}

// ======================= tf32x3 mma.sync GEMM =============================
// C[M,N] = A[M,K] @ B[N,K]^T (+bias).  fp32 in; hi = mask-truncated tf32,
// lo = cvt(x - hi); 3 products (ah*bl + al*bh + ah*bh), fp32 accum.
// Tile 128x128, BK=16, 2-stage cp.async pipeline, 8 warps (32x64 warp tile).
// B fragments processed in 2 halves of 4 nt (regs <= 128 -> 2 CTAs/SM).
#define BM 128
#define BN 128
#define BKc 16
#define LDT 20   // smem row stride in floats

#define CP_ASYNC16(dst_u32, src_ptr) \
    asm volatile("cp.async.cg.shared.global [%0], [%1], 16;" :: "r"(dst_u32), "l"(src_ptr) : "memory")
#define CP_COMMIT() asm volatile("cp.async.commit_group;" ::: "memory")
#define CP_WAIT(n)  asm volatile("cp.async.wait_group %0;" :: "n"(n) : "memory")

__device__ __forceinline__ uint32_t f2tf(float x) {
    uint32_t r; asm("cvt.rna.tf32.f32 %0, %1;" : "=r"(r) : "f"(x));
    return r;
}
// hi via mantissa truncation (exactly tf32-representable), lo via cvt.
__device__ __forceinline__ void split_hl(float x, uint32_t& hi, uint32_t& lo) {
    hi = __float_as_uint(x) & 0xFFFFE000u;
    lo = f2tf(x - __uint_as_float(hi));
}

#define MMA_TF32(c, a, b) \
    asm volatile("mma.sync.aligned.m16n8k8.row.col.f32.tf32.tf32.f32 " \
        "{%0,%1,%2,%3}, {%4,%5,%6,%7}, {%8,%9}, {%0,%1,%2,%3};" \
        : "+f"((c)[0]), "+f"((c)[1]), "+f"((c)[2]), "+f"((c)[3]) \
        : "r"((a)[0]), "r"((a)[1]), "r"((a)[2]), "r"((a)[3]), \
          "r"((b)[0]), "r"((b)[1]))

__global__ void __launch_bounds__(256, 2)
gemm_tf32x3(const float* __restrict__ A, const float* __restrict__ Bw,
            const float* __restrict__ bias, float* __restrict__ C,
            int M, int N, int K)
{
    __shared__ float As[2][BM][LDT];
    __shared__ float Bs[2][BN][LDT];

    const int tid = threadIdx.x;
    const int wid = tid >> 5, lane = tid & 31;
    const int wm = wid >> 1;           // 0..3
    const int wn = wid & 1;            // 0..1
    const int g = lane >> 2;           // 0..7
    const int tg = lane & 3;           // 0..3
    const int bm = blockIdx.y * BM;
    const int bn = blockIdx.x * BN;
    const int NC = K / BKc;            // 48

    uint32_t smA, smB;
    {
        uint32_t a0, b0;
        asm("{ .reg .u64 t; cvta.to.shared.u64 t, %1; cvt.u32.u64 %0, t; }"
            : "=r"(a0) : "l"(&As[0][0][0]));
        asm("{ .reg .u64 t; cvta.to.shared.u64 t, %1; cvt.u32.u64 %0, t; }"
            : "=r"(b0) : "l"(&Bs[0][0][0]));
        smA = a0; smB = b0;
    }

    float acc[2][8][4];
#pragma unroll
    for (int i = 0; i < 2; i++)
#pragma unroll
        for (int j = 0; j < 8; j++)
#pragma unroll
            for (int k = 0; k < 4; k++) acc[i][j][k] = 0.f;

    // ---- load chunk 0 ----
    {
        const int r = tid >> 2, q = tid & 3;
#pragma unroll
        for (int h = 0; h < 2; h++) {
            int rr = r + h * 64;
            CP_ASYNC16(smA + (uint32_t)((0 * BM + rr) * LDT + q * 4) * 4,
                       A + (size_t)(bm + rr) * K + q * 4);
            CP_ASYNC16(smB + (uint32_t)((0 * BN + rr) * LDT + q * 4) * 4,
                       Bw + (size_t)(bn + rr) * K + q * 4);
        }
        CP_COMMIT();
    }

    for (int c = 0; c < NC; ++c) {
        if (c + 1 < NC) {
            const int r = tid >> 2, q = tid & 3;
            const int k0 = (c + 1) * BKc;
            const int nb = (c + 1) & 1;
#pragma unroll
            for (int h = 0; h < 2; h++) {
                int rr = r + h * 64;
                CP_ASYNC16(smA + (uint32_t)((nb * BM + rr) * LDT + q * 4) * 4,
                           A + (size_t)(bm + rr) * K + k0 + q * 4);
                CP_ASYNC16(smB + (uint32_t)((nb * BN + rr) * LDT + q * 4) * 4,
                           Bw + (size_t)(bn + rr) * K + k0 + q * 4);
            }
            CP_COMMIT();
            CP_WAIT(1);
        } else {
            CP_WAIT(0);
        }
        __syncthreads();

        const int cb = c & 1;
#pragma unroll
        for (int ks = 0; ks < 2; ks++) {
            const int kk = ks * 8;
            uint32_t ahi[2][4], alo[2][4];
#pragma unroll
            for (int mt = 0; mt < 2; mt++) {
                const int r0 = wm * 32 + mt * 16 + g;
                float x0 = As[cb][r0][kk + tg];
                float x1 = As[cb][r0 + 8][kk + tg];
                float x2 = As[cb][r0][kk + tg + 4];
                float x3 = As[cb][r0 + 8][kk + tg + 4];
                split_hl(x0, ahi[mt][0], alo[mt][0]);
                split_hl(x1, ahi[mt][1], alo[mt][1]);
                split_hl(x2, ahi[mt][2], alo[mt][2]);
                split_hl(x3, ahi[mt][3], alo[mt][3]);
            }
            // B tiles in two halves of 4 -> lower register pressure,
            // dep distance per accumulator still 8 MMAs.
#pragma unroll
            for (int hb = 0; hb < 2; hb++) {
                uint32_t bhi[4][2], blo[4][2];
#pragma unroll
                for (int nt = 0; nt < 4; nt++) {
                    const int n0 = wn * 64 + (hb * 4 + nt) * 8 + g;
                    float y0 = Bs[cb][n0][kk + tg];
                    float y1 = Bs[cb][n0][kk + tg + 4];
                    split_hl(y0, bhi[nt][0], blo[nt][0]);
                    split_hl(y1, bhi[nt][1], blo[nt][1]);
                }
#pragma unroll
                for (int mt = 0; mt < 2; mt++)
#pragma unroll
                    for (int nt = 0; nt < 4; nt++)
                        MMA_TF32(acc[mt][hb * 4 + nt], ahi[mt], blo[nt]);
#pragma unroll
                for (int mt = 0; mt < 2; mt++)
#pragma unroll
                    for (int nt = 0; nt < 4; nt++)
                        MMA_TF32(acc[mt][hb * 4 + nt], alo[mt], bhi[nt]);
#pragma unroll
                for (int mt = 0; mt < 2; mt++)
#pragma unroll
                    for (int nt = 0; nt < 4; nt++)
                        MMA_TF32(acc[mt][hb * 4 + nt], ahi[mt], bhi[nt]);
            }
        }
        __syncthreads();
    }

    // ---- epilogue ----
#pragma unroll
    for (int mt = 0; mt < 2; mt++) {
        const int r0 = bm + wm * 32 + mt * 16 + g;
#pragma unroll
        for (int nt = 0; nt < 8; nt++) {
            const int n0 = bn + wn * 64 + nt * 8 + tg * 2;
            float bx = 0.f, by = 0.f;
            if (bias) { bx = bias[n0]; by = bias[n0 + 1]; }
            float2 v0 = make_float2(acc[mt][nt][0] + bx, acc[mt][nt][1] + by);
            float2 v1 = make_float2(acc[mt][nt][2] + bx, acc[mt][nt][3] + by);
            *(float2*)(C + (size_t)r0 * N + n0) = v0;
            *(float2*)(C + (size_t)(r0 + 8) * N + n0) = v1;
        }
    }
}

// ======================= elementwise kernels ==============================
__global__ void zero_out_kernel(float4* out, size_t n4)
{
    size_t i = (size_t)blockIdx.x * blockDim.x + threadIdx.x;
    size_t stride = (size_t)gridDim.x * blockDim.x;
    float4 z = make_float4(0.f, 0.f, 0.f, 0.f);
    for (; i < n4; i += stride) out[i] = z;
}

__global__ void init_mask_kernel(const float* __restrict__ x_, int nwords)
{
    int w = blockIdx.x * blockDim.x + threadIdx.x;
    if (w >= nwords) return;
    int b = w >> 7;
    int wa = w & 127;
    const float* xr = x_ + (size_t)b * Asz + wa * 32;
    unsigned int bits = 0;
#pragma unroll
    for (int e = 0; e < 32; e++)
        if (xr[e] != 0.0f) bits |= (1u << e);
    d_mask[w] = bits;
}

// Step 0: h_prev = 0 -> gh = b_hh exactly; h = (1-z)*n.
__global__ void gru_step0_kernel(const float* __restrict__ b_hh, int n)
{
    int i = blockIdx.x * blockDim.x + threadIdx.x;
    if (i >= n) return;
    int b = i / Hsz, k = i - b * Hsz;
    const float* gg = d_Gcls + (size_t)b * G3H;
    float ir = gg[k], iz = gg[Hsz + k], inn = gg[2 * Hsz + k];
    float hr = b_hh[k], hz = b_hh[Hsz + k], hn = b_hh[2 * Hsz + k];
    float r = 1.f / (1.f + expf(-(ir + hr)));
    float z = 1.f / (1.f + expf(-(iz + hz)));
    float nn = tanhf(inn + r * hn);
    d_h[i] = (1.f - z) * nn;
}

// Step j>=1: gi = G_cls + AE_proj[idx_{j-1}]; gh from GEMM (incl. b_hh).
__global__ void gru_step_kernel(int j, int n)
{
    int i = blockIdx.x * blockDim.x + threadIdx.x;
    if (i >= n) return;
    int b = i / Hsz, k = i - b * Hsz;
    int idx = d_idx[(j - 1) * Bsz + b];
    const float* gg = d_Gcls + (size_t)b * G3H;
    const float* ap = d_AEp + (size_t)idx * G3H;
    const float* gh = d_gh + (size_t)b * G3H;
    float ir = gg[k] + ap[k];
    float iz = gg[Hsz + k] + ap[Hsz + k];
    float inn = gg[2 * Hsz + k] + ap[2 * Hsz + k];
    float hr = gh[k], hz = gh[Hsz + k], hn = gh[2 * Hsz + k];
    float r = 1.f / (1.f + expf(-(ir + hr)));
    float z = 1.f / (1.f + expf(-(iz + hz)));
    float nn = tanhf(inn + r * hn);
    d_h[i] = (1.f - z) * nn + z * d_h[i];
}

// ---------------- selection: gumbel + mask + argmax -----------------------
__global__ __launch_bounds__(256) void select_step_kernel(
    const float* __restrict__ x_, float* __restrict__ out,
    int j, unsigned int sk0, unsigned int sk1)
{
    int b = blockIdx.x;
    int t = threadIdx.x;
    __shared__ float sv[256];
    __shared__ int si[256];
    __shared__ int s_done;

    if (j > 0) {
        if (t == 0) {
            int p = d_idx[(j - 1) * Bsz + b];
            s_done = (p == 0);
            if (p == 0) {
                d_idx[j * Bsz + b] = 0;
                out[((size_t)b * Lsz + j) * Asz + 0] = 1.0f;
            }
        }
        __syncthreads();
        if (s_done) return;
    }

    float best = __int_as_float(0xff800000);
    int bidx = 0x7fffffff;
    const float* lrow = d_logits + (size_t)b * Asz;
    const unsigned int* mrow = d_mask + (size_t)b * (Asz / 32);

    for (int a = t; a < Asz; a += 256) {          // coalesced stride
        bool valid;
        if (j == 0) valid = (x_[(size_t)b * Asz + a] != 0.0f);
        else        valid = (a == 0) || ((mrow[a >> 5] >> (a & 31)) & 1u);
        if (!valid) continue;

        unsigned long long p = (unsigned long long)b * Asz + (unsigned long long)a;
        unsigned int y0, y1, bits;
#if GUMBEL_PARTITIONABLE
        threefry2x32(sk0, sk1, (unsigned int)(p >> 32), (unsigned int)p, y0, y1);
        bits = y0 ^ y1;
#else
        const unsigned long long NH = (unsigned long long)Bsz * Asz / 2;
        if (p < NH) { threefry2x32(sk0, sk1, (unsigned int)p, (unsigned int)(p + NH), y0, y1); bits = y0; }
        else        { threefry2x32(sk0, sk1, (unsigned int)(p - NH), (unsigned int)p, y0, y1); bits = y1; }
#endif
        float u = __uint_as_float((bits >> 9) | 0x3f800000u) - 1.0f;
        u = fmaxf(u, 1.17549435e-38f);
        float gmb = -logf(-logf(u));
        float v = lrow[a] + gmb;
        if (v > best || (v == best && a < bidx)) { best = v; bidx = a; }
    }

    sv[t] = best; si[t] = bidx;
    __syncthreads();
    for (int s = 128; s > 0; s >>= 1) {
        if (t < s) {
            float v2 = sv[t + s]; int i2 = si[t + s];
            if (v2 > sv[t] || (v2 == sv[t] && i2 < si[t])) { sv[t] = v2; si[t] = i2; }
        }
        __syncthreads();
    }
    if (t == 0) {
        int sel = (si[0] == 0x7fffffff) ? 0 : si[0];
        d_idx[j * Bsz + b] = sel;
        d_mask[(size_t)b * (Asz / 32) + (sel >> 5)] &= ~(1u << (sel & 31));
        out[((size_t)b * Lsz + j) * Asz + sel] = 1.0f;
    }
}

// ======================= launch ===========================================
extern "C" void kernel_launch(void* const* d_in, const int* in_sizes, int n_in,
                              void* d_out, int out_size)
{
    const float* cls    = (const float*)d_in[0];
    const float* x_     = (const float*)d_in[1];
    const float* w_ih   = (const float*)d_in[2];
    const float* w_hh   = (const float*)d_in[3];
    const float* b_ih   = (const float*)d_in[4];
    const float* b_hh   = (const float*)d_in[5];
    const float* head_w = (const float*)d_in[6];
    const float* head_b = (const float*)d_in[7];
    const float* ae_w   = (const float*)d_in[8];
    float* out = (float*)d_out;

    float *p_Gcls, *p_AEp, *p_gh, *p_h, *p_logits;
    cudaGetSymbolAddress((void**)&p_Gcls,   d_Gcls);
    cudaGetSymbolAddress((void**)&p_AEp,    d_AEp);
    cudaGetSymbolAddress((void**)&p_gh,     d_gh);
    cudaGetSymbolAddress((void**)&p_h,      d_h);
    cudaGetSymbolAddress((void**)&p_logits, d_logits);

    // JAX key chain
    unsigned int k0 = 0u, k1 = 42u;
    unsigned int sub[Lsz][2];
    for (int j = 0; j < Lsz; j++) {
#if GUMBEL_PARTITIONABLE
        unsigned int nk0, nk1, s0, s1;
        threefry2x32(k0, k1, 0u, 0u, nk0, nk1);
        threefry2x32(k0, k1, 0u, 1u, s0, s1);
        sub[j][0] = s0; sub[j][1] = s1; k0 = nk0; k1 = nk1;
#else
        unsigned int a0, a1, c0, c1;
        threefry2x32(k0, k1, 0u, 2u, a0, a1);
        threefry2x32(k0, k1, 1u, 3u, c0, c1);
        sub[j][0] = a1; sub[j][1] = c1;
        k0 = a0; k1 = c0;
#endif
    }

    const int BH = Bsz * Hsz;

    zero_out_kernel<<<4096, 256>>>((float4*)out, (size_t)out_size / 4);
    init_mask_kernel<<<(Bsz * Asz / 32 + 255) / 256, 256>>>(x_, Bsz * Asz / 32);

    dim3 gGates(G3H / BN, Bsz / BM);   // (18, 32)
    dim3 gHead(Asz / BN, Bsz / BM);    // (32, 32)

    // Precompute (once): G_cls = cls @ w_ih^T + b_ih ; AE_proj = ae_w @ w_ih^T
    gemm_tf32x3<<<gGates, 256>>>(cls,  w_ih, b_ih,   p_Gcls, Bsz, G3H, Hsz);
    gemm_tf32x3<<<gGates, 256>>>(ae_w, w_ih, nullptr, p_AEp, Asz, G3H, Hsz);

    // Step 0
    gru_step0_kernel<<<(BH + 255) / 256, 256>>>(b_hh, BH);
    gemm_tf32x3<<<gHead, 256>>>(p_h, head_w, head_b, p_logits, Bsz, Asz, Hsz);
    select_step_kernel<<<Bsz, 256>>>(x_, out, 0, sub[0][0], sub[0][1]);

    for (int j = 1; j < Lsz; j++) {
        gemm_tf32x3<<<gGates, 256>>>(p_h, w_hh, b_hh, p_gh, Bsz, G3H, Hsz);
        gru_step_kernel<<<(BH + 255) / 256, 256>>>(j, BH);
        gemm_tf32x3<<<gHead, 256>>>(p_h, head_w, head_b, p_logits, Bsz, Asz, Hsz);
        select_step_kernel<<<Bsz, 256>>>(x_, out, j, sub[j][0], sub[j][1]);
    }
}